// round 1
// baseline (speedup 1.0000x reference)
#include <cuda_runtime.h>

#define CH_L   4096
#define CH_T   128     // threads per block
#define CH_SEG 32      // CH_L / CH_T
#define NEG_INF (-1e30f)

struct M2 { float a00, a01, a10, a11; };  // max-plus 2x2 operator

// one BP step in log domain: m' = T_c(m)
__device__ __forceinline__ void step_vec(float& m0, float& m1, float c, float a) {
    float x0 = m0 - c;
    float x1 = m1 + c;
    m0 = fmaxf(x0 + a, x1 - a);
    m1 = fmaxf(x0 - a, x1 + a);
}

// apply step to a matrix (compose T_c on the left): columns transform independently
__device__ __forceinline__ void step_mat(M2& M, float c, float a) {
    step_vec(M.a00, M.a10, c, a);   // column 0
    step_vec(M.a01, M.a11, c, a);   // column 1
}

// C = A ∘ B  (B applied first):  C[k][l] = max_m (A[k][m] + B[m][l])
__device__ __forceinline__ M2 compose(const M2& A, const M2& B) {
    M2 C;
    C.a00 = fmaxf(A.a00 + B.a00, A.a01 + B.a10);
    C.a01 = fmaxf(A.a00 + B.a01, A.a01 + B.a11);
    C.a10 = fmaxf(A.a10 + B.a00, A.a11 + B.a10);
    C.a11 = fmaxf(A.a10 + B.a01, A.a11 + B.a11);
    return C;
}

// bank-conflict-free swizzle for the [L] belief arrays:
// replay writes (t = i*32+k across threads i) and epilogue reads (t consecutive)
// both hit distinct banks.
__device__ __forceinline__ int swz(int t) {
    return (t & ~31) | ((t + (t >> 5)) & 31);
}

__global__ __launch_bounds__(CH_T)
void chain_bp_kernel(const float* __restrict__ jp,
                     const float* __restrict__ bp,
                     const int*   __restrict__ obs,
                     float*       __restrict__ out) {
    __shared__ unsigned int sbits[CH_T];   // 1 bit per position
    __shared__ float sb0[CH_L];            // log-belief state 0 (swizzled)
    __shared__ float sb1[CH_L];            // log-belief state 1 (swizzled)
    __shared__ float sm0[CH_T], sm1[CH_T], sm2[CH_T], sm3[CH_T];  // scan matrices (SoA)

    const int row = blockIdx.x;
    const int tid = threadIdx.x;

    const float a  = 0.25f * jp[0];
    const float c0 = 0.5f  * bp[0];
    const float c1 = 0.5f  * bp[1];

    // ---- 1. coalesced obs load -> 1-bit mask per position via ballot ----
    const int* orow = obs + (size_t)row * CH_L;
    #pragma unroll
    for (int t = tid; t < CH_L; t += CH_T) {
        int o = orow[t];
        unsigned int bal = __ballot_sync(0xffffffffu, o != 0);
        if ((tid & 31) == 0) sbits[t >> 5] = bal;
    }
    __syncthreads();

    const unsigned int w     = sbits[tid];                          // my segment's bits
    const unsigned int wnext = (tid < CH_T - 1) ? sbits[tid + 1] : 0u;
    const int base = tid * CH_SEG;

    // ---- 2. forward segment operator:  F_i = T_{c(base+31)} ∘ ... ∘ T_{c(base)} ----
    M2 F = {0.f, NEG_INF, NEG_INF, 0.f};
    #pragma unroll
    for (int k = 0; k < CH_SEG; k++) {
        float c = ((w >> k) & 1u) ? c1 : c0;
        step_mat(F, c, a);
    }

    // ---- 3. Kogge-Stone inclusive PREFIX scan of F (compose with left) ----
    M2 cur = F;
    sm0[tid] = cur.a00; sm1[tid] = cur.a01; sm2[tid] = cur.a10; sm3[tid] = cur.a11;
    #pragma unroll
    for (int off = 1; off < CH_T; off <<= 1) {
        __syncthreads();
        M2 left;
        bool act = (tid >= off);
        if (act) {
            left.a00 = sm0[tid - off]; left.a01 = sm1[tid - off];
            left.a10 = sm2[tid - off]; left.a11 = sm3[tid - off];
        }
        __syncthreads();
        if (act) {
            cur = compose(cur, left);
            sm0[tid] = cur.a00; sm1[tid] = cur.a01; sm2[tid] = cur.a10; sm3[tid] = cur.a11;
        }
    }
    __syncthreads();
    // exclusive: incoming forward message at position base = S[tid-1] applied to (0,0)
    float f0 = 0.f, f1 = 0.f;
    if (tid > 0) {
        f0 = fmaxf(sm0[tid - 1], sm1[tid - 1]);
        f1 = fmaxf(sm2[tid - 1], sm3[tid - 1]);
    }
    __syncthreads();   // done reading prefix results; smem reused for suffix scan

    // ---- 4. backward segment operator: steps t = base+32 down to base+1, skip t==L ----
    M2 Bm = {0.f, NEG_INF, NEG_INF, 0.f};
    if (tid < CH_T - 1) {                      // t = base+32 -> bit 0 of next word
        float c = (wnext & 1u) ? c1 : c0;
        step_mat(Bm, c, a);
    }
    #pragma unroll
    for (int kk = CH_SEG - 1; kk >= 1; kk--) { // t = base+kk
        float c = ((w >> kk) & 1u) ? c1 : c0;
        step_mat(Bm, c, a);
    }

    // ---- 5. Kogge-Stone inclusive SUFFIX scan of B (compose with right) ----
    cur = Bm;
    sm0[tid] = cur.a00; sm1[tid] = cur.a01; sm2[tid] = cur.a10; sm3[tid] = cur.a11;
    #pragma unroll
    for (int off = 1; off < CH_T; off <<= 1) {
        __syncthreads();
        M2 right;
        bool act = (tid + off < CH_T);
        if (act) {
            right.a00 = sm0[tid + off]; right.a01 = sm1[tid + off];
            right.a10 = sm2[tid + off]; right.a11 = sm3[tid + off];
        }
        __syncthreads();
        if (act) {
            cur = compose(cur, right);
            sm0[tid] = cur.a00; sm1[tid] = cur.a01; sm2[tid] = cur.a10; sm3[tid] = cur.a11;
        }
    }
    __syncthreads();
    // incoming backward message = bwd[base+32] = S[tid+1] applied to (0,0); last thread -> (0,0)
    float g0 = 0.f, g1 = 0.f;
    if (tid < CH_T - 1) {
        g0 = fmaxf(sm0[tid + 1], sm1[tid + 1]);
        g1 = fmaxf(sm2[tid + 1], sm3[tid + 1]);
    }

    // ---- 6. forward replay: write lphi + lfwd into shared ----
    float m0 = f0, m1 = f1;
    #pragma unroll
    for (int k = 0; k < CH_SEG; k++) {
        float c = ((w >> k) & 1u) ? c1 : c0;
        int idx = swz(base + k);
        sb0[idx] = m0 - c;          // lphi[t][0] + lfwd[t][0]
        sb1[idx] = m1 + c;          // lphi[t][1] + lfwd[t][1]
        step_vec(m0, m1, c, a);     // fwd[t+1] = T_{c_t}(fwd[t])
    }

    // ---- 7. backward replay: accumulate lbwd into shared ----
    m0 = g0; m1 = g1;
    {   // t = base+31 : uses c at t+1 = base+32 (skip for last thread: bwd[L-1]=(0,0))
        if (tid < CH_T - 1) {
            float c = (wnext & 1u) ? c1 : c0;
            step_vec(m0, m1, c, a);
        }
        int idx = swz(base + CH_SEG - 1);
        sb0[idx] += m0; sb1[idx] += m1;
    }
    #pragma unroll
    for (int k = CH_SEG - 2; k >= 0; k--) {   // t = base+k, uses c at t+1 (bit k+1 of w)
        float c = ((w >> (k + 1)) & 1u) ? c1 : c0;
        step_vec(m0, m1, c, a);
        int idx = swz(base + k);
        sb0[idx] += m0; sb1[idx] += m1;
    }
    __syncthreads();

    // ---- 8. coalesced epilogue: exp and store out[row][s][l] ----
    float* o0 = out + (size_t)row * 2 * CH_L;
    float* o1 = o0 + CH_L;
    #pragma unroll
    for (int t = tid; t < CH_L; t += CH_T) {
        int idx = swz(t);
        o0[t] = __expf(sb0[idx]);
        o1[t] = __expf(sb1[idx]);
    }
}

extern "C" void kernel_launch(void* const* d_in, const int* in_sizes, int n_in,
                              void* d_out, int out_size) {
    const float* jp  = (const float*)d_in[0];
    const float* bp  = (const float*)d_in[1];
    const int*   obs = (const int*)  d_in[2];
    float*       out = (float*)d_out;

    int B = in_sizes[2] / CH_L;
    chain_bp_kernel<<<B, CH_T>>>(jp, bp, obs, out);
}

// round 2
// speedup vs baseline: 1.1346x; 1.1346x over previous
#include <cuda_runtime.h>

#define CH_L   4096
#define CH_T   128     // threads per block
#define CH_SEG 32      // CH_L / CH_T
#define NEG_INF (-1e30f)

struct M2 { float a00, a01, a10, a11; };  // max-plus 2x2 operator

// one BP step in log domain: m' = T_c(m)
__device__ __forceinline__ void step_vec(float& m0, float& m1, float c, float a) {
    float x0 = m0 - c;
    float x1 = m1 + c;
    m0 = fmaxf(x0 + a, x1 - a);
    m1 = fmaxf(x0 - a, x1 + a);
}

// M <- T_c ∘ M  (apply T_c to each column)
__device__ __forceinline__ void step_mat(M2& M, float c, float a) {
    step_vec(M.a00, M.a10, c, a);
    step_vec(M.a01, M.a11, c, a);
}

// C = A ∘ B  (B applied first):  C[k][l] = max_m (A[k][m] + B[m][l])
__device__ __forceinline__ M2 compose(const M2& A, const M2& B) {
    M2 C;
    C.a00 = fmaxf(A.a00 + B.a00, A.a01 + B.a10);
    C.a01 = fmaxf(A.a00 + B.a01, A.a01 + B.a11);
    C.a10 = fmaxf(A.a10 + B.a00, A.a11 + B.a10);
    C.a11 = fmaxf(A.a10 + B.a01, A.a11 + B.a11);
    return C;
}

__device__ __forceinline__ M2 m2_identity() { return M2{0.f, NEG_INF, NEG_INF, 0.f}; }

// ---- 8-step operator table: g_tab[x] = T_{b7} ∘ ... ∘ T_{b0}, b_k = bit k of x ----
__device__ float4 g_tab[256];

__global__ void build_tab_kernel(const float* __restrict__ jp,
                                 const float* __restrict__ bp) {
    int x = threadIdx.x;
    float a  = 0.25f * jp[0];
    float c0 = 0.5f  * bp[0];
    float c1 = 0.5f  * bp[1];
    M2 M = m2_identity();
    #pragma unroll
    for (int k = 0; k < 8; k++) {
        float c = ((x >> k) & 1) ? c1 : c0;
        step_mat(M, c, a);
    }
    g_tab[x] = make_float4(M.a00, M.a01, M.a10, M.a11);
}

__device__ __forceinline__ M2 ld_tab(int i) {
    float4 v = g_tab[i];
    return M2{v.x, v.y, v.z, v.w};
}

__device__ __forceinline__ M2 shfl_up_m2(M2 m, int d) {
    M2 r;
    r.a00 = __shfl_up_sync(0xffffffffu, m.a00, d);
    r.a01 = __shfl_up_sync(0xffffffffu, m.a01, d);
    r.a10 = __shfl_up_sync(0xffffffffu, m.a10, d);
    r.a11 = __shfl_up_sync(0xffffffffu, m.a11, d);
    return r;
}
__device__ __forceinline__ M2 shfl_dn_m2(M2 m, int d) {
    M2 r;
    r.a00 = __shfl_down_sync(0xffffffffu, m.a00, d);
    r.a01 = __shfl_down_sync(0xffffffffu, m.a01, d);
    r.a10 = __shfl_down_sync(0xffffffffu, m.a10, d);
    r.a11 = __shfl_down_sync(0xffffffffu, m.a11, d);
    return r;
}

// bank-conflict-free swizzle for the [L] belief arrays
__device__ __forceinline__ int swz(int t) {
    return (t & ~31) | ((t + (t >> 5)) & 31);
}

__global__ __launch_bounds__(CH_T)
void chain_bp_kernel(const float* __restrict__ jp,
                     const float* __restrict__ bp,
                     const int*   __restrict__ obs,
                     float*       __restrict__ out) {
    __shared__ unsigned int sbits[CH_T];
    __shared__ float sb0[CH_L];            // log-belief state 0 (swizzled)
    __shared__ float sb1[CH_L];            // log-belief state 1 (swizzled)
    __shared__ float4 s_wtF[4];            // per-warp forward totals
    __shared__ float4 s_wtB[4];            // per-warp backward totals

    const int row  = blockIdx.x;
    const int tid  = threadIdx.x;
    const int lane = tid & 31;
    const int wp   = tid >> 5;

    const float a  = 0.25f * jp[0];
    const float c0 = 0.5f  * bp[0];
    const float c1 = 0.5f  * bp[1];

    // ---- 1. coalesced obs load -> 1-bit mask per position via ballot ----
    const int* orow = obs + (size_t)row * CH_L;
    #pragma unroll
    for (int t = tid; t < CH_L; t += CH_T) {
        int o = orow[t];
        unsigned int bal = __ballot_sync(0xffffffffu, o != 0);
        if ((tid & 31) == 0) sbits[t >> 5] = bal;
    }
    __syncthreads();

    const unsigned int w = sbits[tid];     // my 32 positions' bits
    const int base = tid * CH_SEG;

    // ---- 2. forward segment operator from table: F = T_{b31} ∘ ... ∘ T_{b0} ----
    M2 tb0 = ld_tab( w        & 255u);
    M2 tb1 = ld_tab((w >>  8) & 255u);
    M2 tb2 = ld_tab((w >> 16) & 255u);
    M2 tb3 = ld_tab((w >> 24) & 255u);
    M2 F = compose(tb3, compose(tb2, compose(tb1, tb0)));

    // ---- 3. warp-level inclusive PREFIX scan (compose with left) ----
    M2 cur = F;
    #pragma unroll
    for (int off = 1; off < 32; off <<= 1) {
        M2 l = shfl_up_m2(cur, off);
        if (lane >= off) cur = compose(cur, l);
    }
    if (lane == 31) s_wtF[wp] = make_float4(cur.a00, cur.a01, cur.a10, cur.a11);
    __syncthreads();

    // cross-warp forward carry (prefix of earlier warp totals)
    M2 carryF = m2_identity();
    {
        M2 W0 = M2{s_wtF[0].x, s_wtF[0].y, s_wtF[0].z, s_wtF[0].w};
        M2 W1 = M2{s_wtF[1].x, s_wtF[1].y, s_wtF[1].z, s_wtF[1].w};
        M2 W2 = M2{s_wtF[2].x, s_wtF[2].y, s_wtF[2].z, s_wtF[2].w};
        M2 P0 = W0;
        M2 P1 = compose(W1, P0);
        M2 P2 = compose(W2, P1);
        if      (wp == 1) carryF = P0;
        else if (wp == 2) carryF = P1;
        else if (wp == 3) carryF = P2;
    }
    // f = fwd message at position base: apply S[tid-1] (global exclusive) to (0,0)
    float f0 = 0.f, f1 = 0.f;
    {
        M2 sp = shfl_up_m2(cur, 1);
        M2 G;
        if (tid == 0)       G = m2_identity();
        else if (lane == 0) G = carryF;
        else                G = compose(sp, carryF);
        f0 = fmaxf(G.a00, G.a01);
        f1 = fmaxf(G.a10, G.a11);
    }

    // ---- 4. backward segment operator: B' = T_{b0} ∘ T_{b1} ∘ ... ∘ T_{b31} ----
    // (bit 31 applied first) = byte-reversed-bit table lookups
    M2 uB0 = ld_tab(__brev( w        & 255u) >> 24);
    M2 uB1 = ld_tab(__brev((w >>  8) & 255u) >> 24);
    M2 uB2 = ld_tab(__brev((w >> 16) & 255u) >> 24);
    M2 uB3 = ld_tab(__brev((w >> 24) & 255u) >> 24);
    M2 Bm = compose(uB0, compose(uB1, compose(uB2, uB3)));

    // ---- 5. warp-level inclusive SUFFIX scan (compose with right) ----
    cur = Bm;
    #pragma unroll
    for (int off = 1; off < 32; off <<= 1) {
        M2 r = shfl_dn_m2(cur, off);
        if (lane + off < 32) cur = compose(cur, r);
    }
    if (lane == 0) s_wtB[wp] = make_float4(cur.a00, cur.a01, cur.a10, cur.a11);
    __syncthreads();

    // cross-warp backward carry (suffix of later warp totals)
    M2 carryB = m2_identity();
    {
        M2 V1 = M2{s_wtB[1].x, s_wtB[1].y, s_wtB[1].z, s_wtB[1].w};
        M2 V2 = M2{s_wtB[2].x, s_wtB[2].y, s_wtB[2].z, s_wtB[2].w};
        M2 V3 = M2{s_wtB[3].x, s_wtB[3].y, s_wtB[3].z, s_wtB[3].w};
        M2 Q2 = V3;
        M2 Q1 = compose(V2, Q2);
        M2 Q0 = compose(V1, Q1);
        if      (wp == 0) carryB = Q0;
        else if (wp == 1) carryB = Q1;
        else if (wp == 2) carryB = Q2;
    }
    // g = bwd message at position base+31: apply S'[tid+1] to (0,0)
    float g0 = 0.f, g1 = 0.f;
    {
        M2 sn = shfl_dn_m2(cur, 1);
        M2 G;
        if (tid == CH_T - 1)  G = m2_identity();
        else if (lane == 31)  G = carryB;
        else                  G = compose(sn, carryB);
        g0 = fmaxf(G.a00, G.a01);
        g1 = fmaxf(G.a10, G.a11);
    }

    // ---- 6. forward replay: write lphi + lfwd into shared ----
    float m0 = f0, m1 = f1;
    #pragma unroll
    for (int k = 0; k < CH_SEG; k++) {
        float c = ((w >> k) & 1u) ? c1 : c0;
        int idx = swz(base + k);
        sb0[idx] = m0 - c;          // lphi[t][0] + lfwd[t][0]
        sb1[idx] = m1 + c;          // lphi[t][1] + lfwd[t][1]
        step_vec(m0, m1, c, a);
    }

    // ---- 7. backward replay: accumulate lbwd into shared ----
    m0 = g0; m1 = g1;               // bwd at position base+31
    {
        int idx = swz(base + CH_SEG - 1);
        sb0[idx] += m0; sb1[idx] += m1;
    }
    #pragma unroll
    for (int k = CH_SEG - 2; k >= 0; k--) {   // bwd[base+k] = T_{c[base+k+1]}(m)
        float c = ((w >> (k + 1)) & 1u) ? c1 : c0;
        step_vec(m0, m1, c, a);
        int idx = swz(base + k);
        sb0[idx] += m0; sb1[idx] += m1;
    }
    __syncthreads();

    // ---- 8. vectorized epilogue: exp + float4 stores ----
    float4* o0 = (float4*)(out + (size_t)row * 2 * CH_L);
    float4* o1 = (float4*)(out + (size_t)row * 2 * CH_L + CH_L);
    #pragma unroll
    for (int t4 = tid * 4; t4 < CH_L; t4 += CH_T * 4) {
        float4 v0, v1;
        v0.x = __expf(sb0[swz(t4 + 0)]);
        v0.y = __expf(sb0[swz(t4 + 1)]);
        v0.z = __expf(sb0[swz(t4 + 2)]);
        v0.w = __expf(sb0[swz(t4 + 3)]);
        v1.x = __expf(sb1[swz(t4 + 0)]);
        v1.y = __expf(sb1[swz(t4 + 1)]);
        v1.z = __expf(sb1[swz(t4 + 2)]);
        v1.w = __expf(sb1[swz(t4 + 3)]);
        o0[t4 >> 2] = v0;
        o1[t4 >> 2] = v1;
    }
}

extern "C" void kernel_launch(void* const* d_in, const int* in_sizes, int n_in,
                              void* d_out, int out_size) {
    const float* jp  = (const float*)d_in[0];
    const float* bp  = (const float*)d_in[1];
    const int*   obs = (const int*)  d_in[2];
    float*       out = (float*)d_out;

    int B = in_sizes[2] / CH_L;
    build_tab_kernel<<<1, 256>>>(jp, bp);
    chain_bp_kernel<<<B, CH_T>>>(jp, bp, obs, out);
}

// round 3
// speedup vs baseline: 1.3136x; 1.1577x over previous
#include <cuda_runtime.h>

#define CH_L   4096
#define CH_T   128
#define NEG_INF (-1e30f)
#define LOG2E  1.4426950408889634f

typedef unsigned long long u64;

struct M2 { float a00, a01, a10, a11; };  // max-plus 2x2 operator (log2 domain)

__device__ __forceinline__ void step_vec(float& m0, float& m1, float c, float a) {
    float x0 = m0 - c;
    float x1 = m1 + c;
    m0 = fmaxf(x0 + a, x1 - a);
    m1 = fmaxf(x0 - a, x1 + a);
}
__device__ __forceinline__ void step_mat(M2& M, float c, float a) {
    step_vec(M.a00, M.a10, c, a);
    step_vec(M.a01, M.a11, c, a);
}
// C = A ∘ B (B first): C[k][l] = max_m (A[k][m] + B[m][l])
__device__ __forceinline__ M2 compose(const M2& A, const M2& B) {
    M2 C;
    C.a00 = fmaxf(A.a00 + B.a00, A.a01 + B.a10);
    C.a01 = fmaxf(A.a00 + B.a01, A.a01 + B.a11);
    C.a10 = fmaxf(A.a10 + B.a00, A.a11 + B.a10);
    C.a11 = fmaxf(A.a10 + B.a01, A.a11 + B.a11);
    return C;
}
__device__ __forceinline__ M2 m2_identity() { return M2{0.f, NEG_INF, NEG_INF, 0.f}; }

// ---- packed f32x2 helpers ----
__device__ __forceinline__ u64 pk2(float lo, float hi) {
    u64 r; asm("mov.b64 %0, {%1,%2};" : "=l"(r) : "f"(lo), "f"(hi)); return r;
}
__device__ __forceinline__ void upk2(float& lo, float& hi, u64 v) {
    asm("mov.b64 {%0,%1}, %2;" : "=f"(lo), "=f"(hi) : "l"(v));
}
__device__ __forceinline__ u64 fadd2(u64 a, u64 b) {
    u64 r; asm("add.rn.f32x2 %0, %1, %2;" : "=l"(r) : "l"(a), "l"(b)); return r;
}
__device__ __forceinline__ float ex2(float x) {
    float r; asm("ex2.approx.f32 %0, %1;" : "=f"(r) : "f"(x)); return r;
}
// one packed BP step: m' = T(m); also exposes x = m + dc
__device__ __forceinline__ u64 step2(u64 m, u64 dc, u64 aa, u64 na) {
    u64 x = fadd2(m, dc);
    u64 p = fadd2(x, aa), q = fadd2(x, na);
    float pl, ph, ql, qh; upk2(pl, ph, p); upk2(ql, qh, q);
    return pk2(fmaxf(pl, qh), fmaxf(ql, ph));
}

// ---- 8-step operator table: g_tab[x] = T_{b7} ∘ ... ∘ T_{b0} (log2 domain) ----
__device__ float4 g_tab[256];

__global__ void build_tab_kernel(const float* __restrict__ jp,
                                 const float* __restrict__ bp) {
    int x = threadIdx.x;
    float a  = 0.25f * jp[0] * LOG2E;
    float c0 = 0.5f  * bp[0] * LOG2E;
    float c1 = 0.5f  * bp[1] * LOG2E;
    M2 M = m2_identity();
    #pragma unroll
    for (int k = 0; k < 8; k++) {
        float c = ((x >> k) & 1) ? c1 : c0;
        step_mat(M, c, a);
    }
    g_tab[x] = make_float4(M.a00, M.a01, M.a10, M.a11);
}

__device__ __forceinline__ M2 ld_tab(int i) {
    float4 v = g_tab[i];
    return M2{v.x, v.y, v.z, v.w};
}
__device__ __forceinline__ M2 shfl_up_m2(M2 m, int d) {
    M2 r;
    r.a00 = __shfl_up_sync(0xffffffffu, m.a00, d);
    r.a01 = __shfl_up_sync(0xffffffffu, m.a01, d);
    r.a10 = __shfl_up_sync(0xffffffffu, m.a10, d);
    r.a11 = __shfl_up_sync(0xffffffffu, m.a11, d);
    return r;
}
__device__ __forceinline__ M2 shfl_dn_m2(M2 m, int d) {
    M2 r;
    r.a00 = __shfl_down_sync(0xffffffffu, m.a00, d);
    r.a01 = __shfl_down_sync(0xffffffffu, m.a01, d);
    r.a10 = __shfl_down_sync(0xffffffffu, m.a10, d);
    r.a11 = __shfl_down_sync(0xffffffffu, m.a11, d);
    return r;
}

__global__ __launch_bounds__(CH_T)
void chain_bp_kernel(const float* __restrict__ jp,
                     const float* __restrict__ bp,
                     const int*   __restrict__ obs,
                     float*       __restrict__ out) {
    __shared__ unsigned int sbits[CH_T];
    __shared__ float sb0[CH_L];   // belief scratch state 0 (slot-rotated layout)
    __shared__ float sb1[CH_L];   // belief scratch state 1
    __shared__ float4 s_wtF[4];
    __shared__ float4 s_wtB[4];

    const int row  = blockIdx.x;
    const int tid  = threadIdx.x;
    const int lane = tid & 31;
    const int wp   = tid >> 5;

    const float a  = 0.25f * jp[0] * LOG2E;
    const float c0 = 0.5f  * bp[0] * LOG2E;
    const float c1 = 0.5f  * bp[1] * LOG2E;

    // ---- 1. coalesced obs -> 1 bit per position via ballot ----
    const int* orow = obs + (size_t)row * CH_L;
    #pragma unroll
    for (int t = tid; t < CH_L; t += CH_T) {
        int o = orow[t];
        unsigned int bal = __ballot_sync(0xffffffffu, o != 0);
        if ((tid & 31) == 0) sbits[t >> 5] = bal;
    }
    __syncthreads();

    const unsigned int w = sbits[tid];

    // ---- 2. forward segment operator from table ----
    M2 tb0 = ld_tab( w        & 255u);
    M2 tb1 = ld_tab((w >>  8) & 255u);
    M2 tb2 = ld_tab((w >> 16) & 255u);
    M2 tb3 = ld_tab((w >> 24) & 255u);
    M2 F = compose(tb3, compose(tb2, compose(tb1, tb0)));

    // ---- 3. warp prefix scan + cross-warp carry ----
    M2 cur = F;
    #pragma unroll
    for (int off = 1; off < 32; off <<= 1) {
        M2 l = shfl_up_m2(cur, off);
        if (lane >= off) cur = compose(cur, l);
    }
    if (lane == 31) s_wtF[wp] = make_float4(cur.a00, cur.a01, cur.a10, cur.a11);
    __syncthreads();

    M2 carryF = m2_identity();
    {
        M2 W0 = M2{s_wtF[0].x, s_wtF[0].y, s_wtF[0].z, s_wtF[0].w};
        M2 W1 = M2{s_wtF[1].x, s_wtF[1].y, s_wtF[1].z, s_wtF[1].w};
        M2 W2 = M2{s_wtF[2].x, s_wtF[2].y, s_wtF[2].z, s_wtF[2].w};
        M2 P0 = W0;
        M2 P1 = compose(W1, P0);
        M2 P2 = compose(W2, P1);
        if      (wp == 1) carryF = P0;
        else if (wp == 2) carryF = P1;
        else if (wp == 3) carryF = P2;
    }
    float f0 = 0.f, f1 = 0.f;
    {
        M2 sp = shfl_up_m2(cur, 1);
        M2 G;
        if (tid == 0)       G = m2_identity();
        else if (lane == 0) G = carryF;
        else                G = compose(sp, carryF);
        f0 = fmaxf(G.a00, G.a01);
        f1 = fmaxf(G.a10, G.a11);
    }

    // ---- 4. backward segment operator (reverse order = bit-reversed bytes) ----
    M2 uB0 = ld_tab(__brev( w        & 255u) >> 24);
    M2 uB1 = ld_tab(__brev((w >>  8) & 255u) >> 24);
    M2 uB2 = ld_tab(__brev((w >> 16) & 255u) >> 24);
    M2 uB3 = ld_tab(__brev((w >> 24) & 255u) >> 24);
    M2 Bm = compose(uB0, compose(uB1, compose(uB2, uB3)));

    // ---- 5. warp suffix scan + cross-warp carry ----
    cur = Bm;
    #pragma unroll
    for (int off = 1; off < 32; off <<= 1) {
        M2 r = shfl_dn_m2(cur, off);
        if (lane + off < 32) cur = compose(cur, r);
    }
    if (lane == 0) s_wtB[wp] = make_float4(cur.a00, cur.a01, cur.a10, cur.a11);
    __syncthreads();

    M2 carryB = m2_identity();
    {
        M2 V1 = M2{s_wtB[1].x, s_wtB[1].y, s_wtB[1].z, s_wtB[1].w};
        M2 V2 = M2{s_wtB[2].x, s_wtB[2].y, s_wtB[2].z, s_wtB[2].w};
        M2 V3 = M2{s_wtB[3].x, s_wtB[3].y, s_wtB[3].z, s_wtB[3].w};
        M2 Q2 = V3;
        M2 Q1 = compose(V2, Q2);
        M2 Q0 = compose(V1, Q1);
        if      (wp == 0) carryB = Q0;
        else if (wp == 1) carryB = Q1;
        else if (wp == 2) carryB = Q2;
    }
    float g0 = 0.f, g1 = 0.f;   // bwd message at position base+31
    {
        M2 sn = shfl_dn_m2(cur, 1);
        M2 G;
        if (tid == CH_T - 1)  G = m2_identity();
        else if (lane == 31)  G = carryB;
        else                  G = compose(sn, carryB);
        g0 = fmaxf(G.a00, G.a01);
        g1 = fmaxf(G.a10, G.a11);
    }

    // ---- packed constants ----
    const u64 dc0 = pk2(-c0,  c0);
    const u64 dc1 = pk2(-c1,  c1);
    const u64 aa  = pk2( a,   a);
    const u64 na  = pk2(-a,  -a);

    float4* pb0 = (float4*)sb0;
    float4* pb1 = (float4*)sb1;
    const int rowb = tid * 8;        // float4 units: my 32-float block
    const int rot  = tid & 7;        // 16B-slot rotation (bank-conflict-free)

    // ---- 6. forward replay: x[t] = phi+fwd, buffered 4 steps -> STS.128 ----
    u64 m = pk2(f0, f1);
    #pragma unroll
    for (int k4 = 0; k4 < 8; k4++) {
        float4 v0, v1;
        #pragma unroll
        for (int c = 0; c < 4; c++) {
            const int k = k4 * 4 + c;
            u64 dc = ((w >> k) & 1u) ? dc1 : dc0;
            u64 x = fadd2(m, dc);
            float x0s, x1s; upk2(x0s, x1s, x);
            if (c == 0) { v0.x = x0s; v1.x = x1s; }
            else if (c == 1) { v0.y = x0s; v1.y = x1s; }
            else if (c == 2) { v0.z = x0s; v1.z = x1s; }
            else             { v0.w = x0s; v1.w = x1s; }
            u64 p = fadd2(x, aa), q = fadd2(x, na);
            float pl, ph, ql, qh; upk2(pl, ph, p); upk2(ql, qh, q);
            m = pk2(fmaxf(pl, qh), fmaxf(ql, ph));
        }
        const int slot = (k4 + rot) & 7;
        pb0[rowb + slot] = v0;
        pb1[rowb + slot] = v1;
    }

    // ---- 7. backward replay (self-read, no sync needed): belief = exp2(x + bwd) ----
    u64 n = pk2(g0, g1);   // bwd msg at base+31
    #pragma unroll
    for (int k4 = 7; k4 >= 0; k4--) {
        float4 n0, n1;
        #pragma unroll
        for (int c = 3; c >= 0; c--) {
            const int k = k4 * 4 + c;
            float n0s, n1s; upk2(n0s, n1s, n);
            if (c == 0) { n0.x = n0s; n1.x = n1s; }
            else if (c == 1) { n0.y = n0s; n1.y = n1s; }
            else if (c == 2) { n0.z = n0s; n1.z = n1s; }
            else             { n0.w = n0s; n1.w = n1s; }
            if (k > 0) {
                u64 dc = ((w >> k) & 1u) ? dc1 : dc0;
                n = step2(n, dc, aa, na);
            }
        }
        const int slot = (k4 + rot) & 7;
        float4 fv0 = pb0[rowb + slot];
        float4 fv1 = pb1[rowb + slot];
        // packed adds: float4 = 2 x f32x2
        u64 s0a = fadd2(pk2(fv0.x, fv0.y), pk2(n0.x, n0.y));
        u64 s0b = fadd2(pk2(fv0.z, fv0.w), pk2(n0.z, n0.w));
        u64 s1a = fadd2(pk2(fv1.x, fv1.y), pk2(n1.x, n1.y));
        u64 s1b = fadd2(pk2(fv1.z, fv1.w), pk2(n1.z, n1.w));
        float4 o0v, o1v; float lo, hi;
        upk2(lo, hi, s0a); o0v.x = ex2(lo); o0v.y = ex2(hi);
        upk2(lo, hi, s0b); o0v.z = ex2(lo); o0v.w = ex2(hi);
        upk2(lo, hi, s1a); o1v.x = ex2(lo); o1v.y = ex2(hi);
        upk2(lo, hi, s1b); o1v.z = ex2(lo); o1v.w = ex2(hi);
        pb0[rowb + slot] = o0v;
        pb1[rowb + slot] = o1v;
    }
    __syncthreads();

    // ---- 8. epilogue: pure LDS.128 -> STG.128 coalesced copy ----
    float4* o0 = (float4*)(out + (size_t)row * 2 * CH_L);
    float4* o1 = o0 + (CH_L / 4);
    #pragma unroll
    for (int it = 0; it < 8; it++) {
        const int u   = tid + CH_T * it;   // float4 group index
        const int blk = u >> 3;
        const int k4  = u & 7;
        const int slot = (k4 + (blk & 7)) & 7;
        o0[u] = pb0[blk * 8 + slot];
        o1[u] = pb1[blk * 8 + slot];
    }
}

extern "C" void kernel_launch(void* const* d_in, const int* in_sizes, int n_in,
                              void* d_out, int out_size) {
    const float* jp  = (const float*)d_in[0];
    const float* bp  = (const float*)d_in[1];
    const int*   obs = (const int*)  d_in[2];
    float*       out = (float*)d_out;

    int B = in_sizes[2] / CH_L;
    build_tab_kernel<<<1, 256>>>(jp, bp);
    chain_bp_kernel<<<B, CH_T>>>(jp, bp, obs, out);
}